// round 13
// baseline (speedup 1.0000x reference)
#include <cuda_runtime.h>
#include <cuda_fp16.h>
#include <math.h>
#include <stdint.h>

#define NS    32768
#define DD    32
#define SPLITD 16
#define BINSN 16
#define HID   320
#define POUT  1008
#define LOG2PI_F 1.8378770664093453f

// padded GEMM dims
#define NP12  384     // GEMM2 N padded (real 320)
#define NP3   1024    // GEMM3 N padded (real 1008)

// ================= scratch (device globals; zero-initialized at load) =================
__device__ float g_z[NS * DD];
__device__ float g_ladj[NS * SPLITD];
__device__ __half g_P[(size_t)NS * POUT];

__device__ __half g_H1[NS * HID];
__device__ __half g_H2[NS * HID];

// W1 packed for fused-H1: [layer][kp*320 + c] = half2(W1[2kp][c], W1[2kp+1][c])
__device__ uint32_t g_W1s[2][8 * HID];
__device__ __half g_W2t[2][NP12 * HID];
__device__ __half g_W3t[2][(size_t)NP3 * HID];

// spline1 tables: [layer][dim][bin]
__device__ float g_sknot[2][SPLITD][16];
__device__ float g_sbin[2][SPLITD][BINSN][12];  // ya yb ym iw icw il wb wc dnl dnr pad pad

// ================= helpers =================
__device__ __forceinline__ uint32_t smem_u32(const void* p) {
    uint32_t a;
    asm("{ .reg .u64 t; cvta.to.shared.u64 t, %1; cvt.u32.u64 %0, t; }" : "=r"(a) : "l"(p));
    return a;
}
__device__ __forceinline__ void cp16(uint32_t dst, const void* src) {
    asm volatile("cp.async.cg.shared.global [%0], [%1], 16;" :: "r"(dst), "l"(src));
}
__device__ __forceinline__ void ldsm4(uint32_t& r0, uint32_t& r1, uint32_t& r2, uint32_t& r3, uint32_t a) {
    asm volatile("ldmatrix.sync.aligned.m8n8.x4.shared.b16 {%0,%1,%2,%3}, [%4];"
                 : "=r"(r0), "=r"(r1), "=r"(r2), "=r"(r3) : "r"(a));
}
__device__ __forceinline__ void mma_f16(float* c, const uint32_t* a, const uint32_t* b) {
    asm volatile("mma.sync.aligned.m16n8k16.row.col.f32.f16.f16.f32 "
                 "{%0,%1,%2,%3}, {%4,%5,%6,%7}, {%8,%9}, {%0,%1,%2,%3};"
                 : "+f"(c[0]), "+f"(c[1]), "+f"(c[2]), "+f"(c[3])
                 : "r"(a[0]), "r"(a[1]), "r"(a[2]), "r"(a[3]), "r"(b[0]), "r"(b[1]));
}
__device__ __forceinline__ float tof(__half v) { return __half2float(v); }

// ================= weight prep: BOTH layers, one launch =================
#define SEGW1 (8 * HID)               // 2560 uint32 per layer
#define SEG2  (NP12 * HID)
#define SEG3  (NP3 * HID)
#define PREP_TOT (SEGW1 + SEG2 + SEG3)

__global__ void k_prepall(const float* __restrict__ W1a, const float* __restrict__ W2a,
                          const float* __restrict__ W3a,
                          const float* __restrict__ W1b, const float* __restrict__ W2b,
                          const float* __restrict__ W3b) {
    int gi = blockIdx.x * blockDim.x + threadIdx.x;
    int L = (gi >= PREP_TOT) ? 1 : 0;
    int idx0 = gi - L * PREP_TOT;
    if (idx0 >= PREP_TOT) return;
    if (idx0 < SEGW1) {
        const float* W = L ? W1b : W1a;      // [16][320] row-major
        int kp = idx0 / HID, c = idx0 - kp * HID;
        __half lo = __float2half_rn(W[(2 * kp) * HID + c]);
        __half hi = __float2half_rn(W[(2 * kp + 1) * HID + c]);
        __half2 h2 = __halves2half2(lo, hi);
        g_W1s[L][idx0] = *reinterpret_cast<uint32_t*>(&h2);
    } else if (idx0 < SEGW1 + SEG2) {
        const float* W = L ? W2b : W2a;
        int i2 = idx0 - SEGW1;
        int n = i2 / HID, k = i2 - n * HID;
        float v = (n < HID) ? W[(size_t)k * HID + n] : 0.0f;
        g_W2t[L][i2] = __float2half_rn(v);
    } else {
        const float* W = L ? W3b : W3a;
        int i3 = idx0 - SEGW1 - SEG2;
        int n = i3 / HID, k = i3 - n * HID;
        float v = (n < POUT) ? W[(size_t)k * POUT + n] : 0.0f;
        g_W3t[L][i3] = __float2half_rn(v);
    }
}

// ================= spline1 table precompute (1 block, 512 threads) =================
__device__ __forceinline__ float softplus_fast(float v) {
    return fmaxf(v, 0.0f) + __logf(1.0f + __expf(-fabsf(v)));
}

__global__ void k_prepspline(const float* __restrict__ w0, const float* __restrict__ h0,
                             const float* __restrict__ d0, const float* __restrict__ l0,
                             const float* __restrict__ w1, const float* __restrict__ h1,
                             const float* __restrict__ d1, const float* __restrict__ l1) {
    int t = threadIdx.x;            // 0..511
    int L = t >> 8, j = (t >> 4) & 15, b = t & 15;
    const float* wr = (L ? w1 : w0) + j * BINSN;
    const float* hr = (L ? h1 : h0) + j * BINSN;
    const float* dr = (L ? d1 : d0) + j * (BINSN - 1);
    const float* lr = (L ? l1 : l0) + j * BINSN;

    float w[BINSN], h[BINSN];
#pragma unroll
    for (int k = 0; k < BINSN; k++) { w[k] = wr[k]; h[k] = hr[k]; }
    float hm = h[0], wm = w[0];
#pragma unroll
    for (int k = 1; k < BINSN; k++) { hm = fmaxf(hm, h[k]); wm = fmaxf(wm, w[k]); }
    float hs = 0.f, ws = 0.f;
#pragma unroll
    for (int k = 0; k < BINSN; k++) { h[k] = __expf(h[k] - hm); hs += h[k];
                                      w[k] = __expf(w[k] - wm); ws += w[k]; }
    float hscale = 0.984f / hs, wscale = 0.984f / ws;

    float ich = -3.f, ih = 0.f, icw = -3.f, iw = 0.f;
    {
        float prev = -3.f, cs = 0.f;
#pragma unroll
        for (int k = 0; k < BINSN; k++) {
            float hb = 0.001f + hscale * h[k];
            cs += hb;
            float e = (k == BINSN - 1) ? 3.f : fmaf(6.0f, cs, -3.0f);
            if (k == b) { ich = prev; ih = e - prev; }
            prev = e;
        }
    }
    {
        float prev = -3.f, cs = 0.f;
#pragma unroll
        for (int k = 0; k < BINSN; k++) {
            float wb_ = 0.001f + wscale * w[k];
            cs += wb_;
            float e = (k == BINSN - 1) ? 3.f : fmaf(6.0f, cs, -3.0f);
            if (k == b) { icw = prev; iw = e - prev; }
            prev = e;
        }
    }

    float idv   = (b == 0)         ? 0.999f : (0.001f + softplus_fast(dr[b - 1]));
    float idvp1 = (b == BINSN - 1) ? 0.999f : (0.001f + softplus_fast(dr[b]));
    float il    = 0.025f + 0.95f / (1.0f + __expf(-lr[b]));

    float idel = ih / iw;
    float wb   = sqrtf(idv / idvp1);
    float wc   = (il * idv + (1.0f - il) * wb * idvp1) / idel;
    float ya = ich, yb = ih + ich;
    float ym = ((1.0f - il) * ya + il * wb * yb) / ((1.0f - il) + il * wb);
    float dnl = wc * il * (ym - ya) * iw;
    float dnr = wb * wc * (1.0f - il) * (yb - ym) * iw;

    g_sknot[L][j][b] = ich;
    float* e = &g_sbin[L][j][b][0];
    e[0] = ya; e[1] = yb; e[2] = ym; e[3] = iw; e[4] = icw;
    e[5] = il; e[6] = wb; e[7] = wc; e[8] = dnl; e[9] = dnr;
}

// table-driven spline1 eval
__device__ __forceinline__ void spline1_tab(int L, int j, float y, float& xo, float& lo_) {
    bool inside = (y >= -3.f) && (y <= 3.f);
    float yc = fminf(fmaxf(y, -3.f), 3.f);
    const float* kn = &g_sknot[L][j][0];
    int idx = -1;
#pragma unroll
    for (int k = 0; k < 16; k++) idx += (yc >= kn[k]) ? 1 : 0;
    idx = (idx < 0) ? 0 : idx;
    const float* e = &g_sbin[L][j][idx][0];
    float4 e0 = *reinterpret_cast<const float4*>(e);
    float4 e1 = *reinterpret_cast<const float4*>(e + 4);
    float2 e2 = *reinterpret_cast<const float2*>(e + 8);
    float ya = e0.x, yb = e0.y, ym = e0.z, iw = e0.w;
    float icw = e1.x, il = e1.y, wb = e1.z, wc = e1.w;
    bool left = (yc <= ym);
    float num, den, dn;
    if (left) {
        num = il * (ya - yc);
        den = (wc - 1.0f) * yc + ya - wc * ym;
        dn  = e2.x;
    } else {
        num = (wc - il * wb) * yc + il * wb * yb - wc * ym;
        den = (wc - wb) * yc + wb * yb - wc * ym;
        dn  = e2.y;
    }
    float x  = num / den * iw + icw;
    float la = __logf(dn) - 2.0f * __logf(fabsf(den));
    xo  = inside ? x  : y;
    lo_ = inside ? la : 0.0f;
}

// fused H1 = relu(x1 @ W1 + b1): block = 16 samples x 16 dims
__device__ __forceinline__ void fused_h1(int n, int ln, int j,
                                         const uint32_t* __restrict__ sW1,
                                         const float (*s_x1)[17],
                                         const float* __restrict__ b1) {
    float xv[16];
#pragma unroll
    for (int k = 0; k < 16; k++) xv[k] = s_x1[ln][k];
#pragma unroll 4
    for (int t = 0; t < 20; t++) {
        int c = j + 16 * t;
        float acc = b1[c];
#pragma unroll
        for (int kp = 0; kp < 8; kp++) {
            uint32_t u = sW1[kp * HID + c];
            __half2 h2 = *reinterpret_cast<__half2*>(&u);
            float2 f = __half22float2(h2);
            acc = fmaf(xv[2 * kp], f.x, acc);
            acc = fmaf(xv[2 * kp + 1], f.y, acc);
        }
        acc = fmaxf(acc, 0.f);
        g_H1[n * HID + c] = __float2half_rn(acc);
    }
}

// full per-sample spline inverse (fp16 params from P), fast-math
__device__ __forceinline__ void rls_inv_h(
    float y,
    const __half* __restrict__ wr, const __half* __restrict__ hr,
    const __half* __restrict__ dr, const __half* __restrict__ lr,
    float& xo, float& lo_)
{
    const float BD = 3.0f;
    float w[BINSN], h[BINSN];
#pragma unroll
    for (int b = 0; b < BINSN; b++) { w[b] = tof(wr[b]); h[b] = tof(hr[b]); }

    bool inside = (y >= -BD) && (y <= BD);
    float yc = fminf(fmaxf(y, -BD), BD);

    float hm = h[0], wm = w[0];
#pragma unroll
    for (int b = 1; b < BINSN; b++) { hm = fmaxf(hm, h[b]); wm = fmaxf(wm, w[b]); }
    float hs = 0.f, ws = 0.f;
#pragma unroll
    for (int b = 0; b < BINSN; b++) { h[b] = __expf(h[b] - hm); hs += h[b];
                                      w[b] = __expf(w[b] - wm); ws += w[b]; }
    float hscale = 0.984f / hs;
    float wscale = 0.984f / ws;

    int idx = 0; float ich = -BD, ih = 0.f;
    {
        float prev = -BD, cs = 0.f;
#pragma unroll
        for (int b = 0; b < BINSN; b++) {
            float hb = 0.001f + hscale * h[b];
            cs += hb;
            float e = (b == BINSN - 1) ? BD : fmaf(6.0f, cs, -3.0f);
            if (yc >= prev) { idx = b; ich = prev; ih = e - prev; }
            prev = e;
        }
    }
    float icw = -BD, iw = 0.f;
    {
        float prev = -BD, cs = 0.f;
#pragma unroll
        for (int b = 0; b < BINSN; b++) {
            float wb_ = 0.001f + wscale * w[b];
            cs += wb_;
            float e = (b == BINSN - 1) ? BD : fmaf(6.0f, cs, -3.0f);
            if (b == idx) { icw = prev; iw = e - prev; }
            prev = e;
        }
    }

    float idv   = (idx == 0)         ? 0.999f : (0.001f + softplus_fast(tof(dr[idx - 1])));
    float idvp1 = (idx == BINSN - 1) ? 0.999f : (0.001f + softplus_fast(tof(dr[idx])));
    float il    = 0.025f + 0.95f / (1.0f + __expf(-tof(lr[idx])));

    float idel = ih / iw;
    float wb   = sqrtf(idv / idvp1);
    float wc   = (il * idv + (1.0f - il) * wb * idvp1) / idel;
    float ya = ich, yb = ih + ich;
    float ym = ((1.0f - il) * ya + il * wb * yb) / ((1.0f - il) + il * wb);

    bool left = (yc <= ym);
    float num, den, dnum;
    if (left) {
        num  = il * (ya - yc);
        den  = (wc - 1.0f) * yc + ya - wc * ym;
        dnum = wc * il * (ym - ya) * iw;
    } else {
        num  = (wc - il * wb) * yc + il * wb * yb - wc * ym;
        den  = (wc - wb) * yc + wb * yb - wc * ym;
        dnum = wb * wc * (1.0f - il) * (yb - ym) * iw;
    }
    float x  = num / den * iw + icw;
    float la = __logf(dnum) - 2.0f * __logf(fabsf(den));

    xo  = inside ? x  : y;
    lo_ = inside ? la : 0.0f;
}

__device__ __forceinline__ void spline2_step(int n, int j, float& x2, float& ladj_acc) {
    float y = g_z[n * DD + SPLITD + j];
    const __half* pr = g_P + (size_t)n * POUT;
    float la;
    rls_inv_h(y,
              pr + j * BINSN,
              pr + 256 + j * BINSN,
              pr + 512 + j * (BINSN - 1),
              pr + 752 + j * BINSN,
              x2, la);
    ladj_acc += la;
}

// first kernel: affine prelude + table spline1 of layer 0 + fused H1
__global__ void __launch_bounds__(256) k_first(const float* __restrict__ data,
                        const float* __restrict__ means,
                        const float* __restrict__ stds,
                        const float* __restrict__ b1) {
    __shared__ uint32_t sW1[8 * HID];
    __shared__ float s_x1[16][17];
    int tid = threadIdx.x;
#pragma unroll
    for (int u = tid; u < 8 * HID; u += 256) sW1[u] = g_W1s[0][u];

    int i = blockIdx.x * 256 + tid;
    int n = i >> 4, j = i & 15, ln = tid >> 4;
    float y  = (data[n * DD + j]      - means[j])      / (10.0f * stds[j]);
    float y2 = (data[n * DD + j + 16] - means[j + 16]) / (10.0f * stds[j + 16]);
    g_z[n * DD + j + 16] = y2;
    float x, la;
    spline1_tab(0, j, y, x, la);
    g_z[n * DD + j] = x;
    g_ladj[i] = la;
    s_x1[ln][j] = x;
    __syncthreads();
    fused_h1(n, ln, j, sW1, s_x1, b1);
}

// mid kernel: spline2 of layer 0 + table spline1 of layer 1 + fused H1
__global__ void __launch_bounds__(256) k_mid(const float* __restrict__ b1) {
    __shared__ uint32_t sW1[8 * HID];
    __shared__ float s_x1[16][17];
    int tid = threadIdx.x;
#pragma unroll
    for (int u = tid; u < 8 * HID; u += 256) sW1[u] = g_W1s[1][u];

    int i = blockIdx.x * 256 + tid;
    int n = i >> 4, j = i & 15, ln = tid >> 4;
    float ladj = g_ladj[i];
    float x2;
    spline2_step(n, j, x2, ladj);
    g_z[n * DD + SPLITD + j] = x2;

    float y1 = g_z[n * DD + j];
    float x1, la1;
    spline1_tab(1, j, y1, x1, la1);
    g_z[n * DD + j] = x1;
    g_ladj[i] = ladj + la1;
    s_x1[ln][j] = x1;
    __syncthreads();
    fused_h1(n, ln, j, sW1, s_x1, b1);
}

// last kernel: spline2 of final layer + Gaussian base + lpaff reduction -> out
__global__ void k_last(const float* __restrict__ stds, float* __restrict__ out) {
    __shared__ float s_lp;
    if (threadIdx.x < 32) {
        float v = logf(10.0f * stds[threadIdx.x]);
#pragma unroll
        for (int o = 16; o > 0; o >>= 1) v += __shfl_down_sync(0xffffffffu, v, o);
        if (threadIdx.x == 0) s_lp = -v;
    }
    __syncthreads();
    int i = blockIdx.x * blockDim.x + threadIdx.x;
    int n = i >> 4, j = i & 15;
    float ladj = g_ladj[i];
    float x2;
    spline2_step(n, j, x2, ladj);
    float z1 = g_z[n * DD + j];
    float ss = fmaf(z1, z1, x2 * x2);
#pragma unroll
    for (int o = 1; o < 16; o <<= 1) {
        ss   += __shfl_xor_sync(0xffffffffu, ss, o);
        ladj += __shfl_xor_sync(0xffffffffu, ladj, o);
    }
    if ((threadIdx.x & 15) == 0)
        out[n] = -0.5f * ss - 0.5f * (float)DD * LOG2PI_F + ladj + s_lp;
}

// ====== HMMA fp16 GEMM: CTA tile 256x128, BK=64, 8 warps (4x2), 64x64 warp tiles ====
#define RSTR    144
#define ATILE_B (256 * RSTR)          // 36864
#define BTILE_B (128 * RSTR)          // 18432
#define STAGE_B (ATILE_B + BTILE_B)   // 55296
#define SM_TOTAL (2 * STAGE_B)        // 110592

template <bool RELU>
__global__ void __launch_bounds__(256, 1) hgemm(
    const __half* __restrict__ A,
    const __half* __restrict__ B,
    const float* __restrict__ bias,
    int K, int Nreal, int ldc,
    __half* __restrict__ C)
{
    extern __shared__ char smem[];
    const uint32_t sb = smem_u32(smem);
    const int tid = threadIdx.x;
    const int wid = tid >> 5, lane = tid & 31;
    const int wm = wid >> 1, wn = wid & 1;          // 4x2 warp grid, warp tile 64x64

    const int brow = blockIdx.y * 256;
    const int bcol = blockIdx.x * 128;
    const int nch = K >> 6;

    float acc[4][8][4];
#pragma unroll
    for (int i = 0; i < 4; i++)
#pragma unroll
        for (int j = 0; j < 8; j++)
#pragma unroll
            for (int q = 0; q < 4; q++) acc[i][j][q] = 0.f;

    // per chunk: A 256x64 (2048 units) + B 128x64 (1024 units) = 3072; 12 per thread
    auto load_chunk = [&](int ch, int stage) {
        const int k0 = ch * 64;
        const uint32_t sbase = sb + stage * STAGE_B;
#pragma unroll
        for (int u = 0; u < 12; u++) {
            int idx = tid + u * 256;
            if (idx < 2048) {
                int r = idx >> 3, c = idx & 7;
                uint32_t so = (uint32_t)(r * RSTR + c * 16);
                cp16(sbase + so, A + (size_t)(brow + r) * K + k0 + c * 8);
            } else {
                int wi = idx - 2048;
                int r = wi >> 3, c = wi & 7;
                uint32_t so = (uint32_t)(ATILE_B + r * RSTR + c * 16);
                cp16(sbase + so, B + (size_t)(bcol + r) * K + k0 + c * 8);
            }
        }
        asm volatile("cp.async.commit_group;" ::: "memory");
    };

    load_chunk(0, 0);

    for (int ch = 0; ch < nch; ch++) {
        if (ch + 1 < nch) {
            load_chunk(ch + 1, (ch + 1) & 1);
            asm volatile("cp.async.wait_group 1;" ::: "memory");
        } else {
            asm volatile("cp.async.wait_group 0;" ::: "memory");
        }
        __syncthreads();

        const uint32_t sbase = sb + (ch & 1) * STAGE_B;
        const uint32_t abase = sbase;
        const uint32_t bbase = sbase + ATILE_B;

#pragma unroll
        for (int ks = 0; ks < 4; ks++) {
            uint32_t a[4][4];
            const uint32_t arow = (uint32_t)(wm * 64 + (lane & 15));
            const uint32_t akb  = (uint32_t)(ks * 32 + ((lane >> 4) & 1) * 16);
#pragma unroll
            for (int tm = 0; tm < 4; tm++) {
                uint32_t off = (arow + tm * 16) * RSTR + akb;
                ldsm4(a[tm][0], a[tm][1], a[tm][2], a[tm][3], abase + off);
            }
            uint32_t bf[8][2];
            const uint32_t nrow0 = (uint32_t)(wn * 64 + (lane & 7) + ((lane >> 4) & 1) * 8);
            const uint32_t bkb   = (uint32_t)(ks * 32 + ((lane >> 3) & 1) * 16);
#pragma unroll
            for (int tp = 0; tp < 4; tp++) {
                uint32_t off = (nrow0 + tp * 16) * RSTR + bkb;
                ldsm4(bf[tp * 2][0], bf[tp * 2][1], bf[tp * 2 + 1][0], bf[tp * 2 + 1][1], bbase + off);
            }
#pragma unroll
            for (int tm = 0; tm < 4; tm++)
#pragma unroll
                for (int tn = 0; tn < 8; tn++)
                    mma_f16(acc[tm][tn], a[tm], bf[tn]);
        }
        __syncthreads();
    }

    // epilogue: bias (+ReLU), fp16 output
#pragma unroll
    for (int tm = 0; tm < 4; tm++) {
#pragma unroll
        for (int tn = 0; tn < 8; tn++) {
            int n = bcol + wn * 64 + tn * 8 + 2 * (lane & 3);
            if (n >= Nreal) continue;
            float bb0 = bias[n], bb1 = bias[n + 1];
#pragma unroll
            for (int half = 0; half < 2; half++) {
                int m = brow + wm * 64 + tm * 16 + (lane >> 2) + half * 8;
                float v0 = acc[tm][tn][half * 2 + 0] + bb0;
                float v1 = acc[tm][tn][half * 2 + 1] + bb1;
                if (RELU) { v0 = fmaxf(v0, 0.f); v1 = fmaxf(v1, 0.f); }
                __half2 hv = __floats2half2_rn(v0, v1);
                *reinterpret_cast<__half2*>(C + (size_t)m * ldc + n) = hv;
            }
        }
    }
}

// ================= launch =================
extern "C" void kernel_launch(void* const* d_in, const int* in_sizes, int n_in,
                              void* d_out, int out_size) {
    const float* data  = (const float*)d_in[0];
    const float* means = (const float*)d_in[1];
    const float* stds  = (const float*)d_in[2];

    // slot 0 = t2 (applied first), slot 1 = t1
    const float* tw[2]  = { (const float*)d_in[13], (const float*)d_in[3] };
    const float* th[2]  = { (const float*)d_in[14], (const float*)d_in[4] };
    const float* td[2]  = { (const float*)d_in[15], (const float*)d_in[5] };
    const float* tl[2]  = { (const float*)d_in[16], (const float*)d_in[6] };
    const float* tW1[2] = { (const float*)d_in[17], (const float*)d_in[7] };
    const float* tb1[2] = { (const float*)d_in[18], (const float*)d_in[8] };
    const float* tW2[2] = { (const float*)d_in[19], (const float*)d_in[9] };
    const float* tb2[2] = { (const float*)d_in[20], (const float*)d_in[10] };
    const float* tW3[2] = { (const float*)d_in[21], (const float*)d_in[11] };
    const float* tb3[2] = { (const float*)d_in[22], (const float*)d_in[12] };

    float* out = (float*)d_out;

    __half *H1, *H2, *pP;
    __half *W2t0, *W3t0;
    cudaGetSymbolAddress((void**)&H1,  g_H1);
    cudaGetSymbolAddress((void**)&H2,  g_H2);
    cudaGetSymbolAddress((void**)&pP,  g_P);
    cudaGetSymbolAddress((void**)&W2t0, g_W2t);
    cudaGetSymbolAddress((void**)&W3t0, g_W3t);

    cudaFuncSetAttribute(hgemm<true >, cudaFuncAttributeMaxDynamicSharedMemorySize, SM_TOTAL);
    cudaFuncSetAttribute(hgemm<false>, cudaFuncAttributeMaxDynamicSharedMemorySize, SM_TOTAL);

    const int splineBlocks = (NS * SPLITD) / 256;
    dim3 g12(NP12 / 128, NS / 256);  // (3, 128)
    dim3 g3 (NP3  / 128, NS / 256);  // (8, 128)

    k_prepall<<<(2 * PREP_TOT + 255) / 256, 256>>>(tW1[0], tW2[0], tW3[0],
                                                   tW1[1], tW2[1], tW3[1]);
    k_prepspline<<<1, 512>>>(tw[0], th[0], td[0], tl[0], tw[1], th[1], td[1], tl[1]);

    k_first<<<splineBlocks, 256>>>(data, means, stds, tb1[0]);

    for (int L = 0; L < 2; L++) {
        __half* W2t = W2t0 + (size_t)L * SEG2;
        __half* W3t = W3t0 + (size_t)L * SEG3;

        hgemm<true ><<<g12, 256, SM_TOTAL>>>(H1, W2t, tb2[L], HID, HID, HID, H2);
        hgemm<false><<<g3,  256, SM_TOTAL>>>(H2, W3t, tb3[L], HID, POUT, POUT, pP);

        if (L == 0)
            k_mid<<<splineBlocks, 256>>>(tb1[1]);
        else
            k_last<<<splineBlocks, 256>>>(stds, out);
    }
}

// round 14
// speedup vs baseline: 1.1727x; 1.1727x over previous
#include <cuda_runtime.h>
#include <cuda_fp16.h>
#include <math.h>
#include <stdint.h>

#define NS    32768
#define DD    32
#define SPLITD 16
#define BINSN 16
#define HID   320
#define POUT  1008
#define LOG2PI_F 1.8378770664093453f

#define NP12  384
#define NP3   1024

// ================= scratch =================
__device__ float g_z[NS * DD];
__device__ float g_ladj[NS * SPLITD];
__device__ __half g_P[(size_t)NS * POUT];

__device__ __half g_H1[NS * HID];
__device__ __half g_H2[NS * HID];

__device__ uint32_t g_W1s[2][8 * HID];
__device__ __half g_W2t[2][NP12 * HID];
__device__ __half g_W3t[2][(size_t)NP3 * HID];

__device__ float g_sknot[2][SPLITD][16];
__device__ float g_sbin[2][SPLITD][BINSN][12];

// ================= helpers =================
__device__ __forceinline__ uint32_t smem_u32(const void* p) {
    uint32_t a;
    asm("{ .reg .u64 t; cvta.to.shared.u64 t, %1; cvt.u32.u64 %0, t; }" : "=r"(a) : "l"(p));
    return a;
}
__device__ __forceinline__ void cp16(uint32_t dst, const void* src) {
    asm volatile("cp.async.cg.shared.global [%0], [%1], 16;" :: "r"(dst), "l"(src));
}
__device__ __forceinline__ void ldsm4(uint32_t& r0, uint32_t& r1, uint32_t& r2, uint32_t& r3, uint32_t a) {
    asm volatile("ldmatrix.sync.aligned.m8n8.x4.shared.b16 {%0,%1,%2,%3}, [%4];"
                 : "=r"(r0), "=r"(r1), "=r"(r2), "=r"(r3) : "r"(a));
}
__device__ __forceinline__ void mma_f16(float* c, const uint32_t* a, const uint32_t* b) {
    asm volatile("mma.sync.aligned.m16n8k16.row.col.f32.f16.f16.f32 "
                 "{%0,%1,%2,%3}, {%4,%5,%6,%7}, {%8,%9}, {%0,%1,%2,%3};"
                 : "+f"(c[0]), "+f"(c[1]), "+f"(c[2]), "+f"(c[3])
                 : "r"(a[0]), "r"(a[1]), "r"(a[2]), "r"(a[3]), "r"(b[0]), "r"(b[1]));
}
__device__ __forceinline__ float tof(__half v) { return __half2float(v); }

// ================= weight prep: BOTH layers, one launch =================
#define SEGW1 (8 * HID)
#define SEG2  (NP12 * HID)
#define SEG3  (NP3 * HID)
#define PREP_TOT (SEGW1 + SEG2 + SEG3)

__global__ void k_prepall(const float* __restrict__ W1a, const float* __restrict__ W2a,
                          const float* __restrict__ W3a,
                          const float* __restrict__ W1b, const float* __restrict__ W2b,
                          const float* __restrict__ W3b) {
    int gi = blockIdx.x * blockDim.x + threadIdx.x;
    int L = (gi >= PREP_TOT) ? 1 : 0;
    int idx0 = gi - L * PREP_TOT;
    if (idx0 >= PREP_TOT) return;
    if (idx0 < SEGW1) {
        const float* W = L ? W1b : W1a;
        int kp = idx0 / HID, c = idx0 - kp * HID;
        __half lo = __float2half_rn(W[(2 * kp) * HID + c]);
        __half hi = __float2half_rn(W[(2 * kp + 1) * HID + c]);
        __half2 h2 = __halves2half2(lo, hi);
        g_W1s[L][idx0] = *reinterpret_cast<uint32_t*>(&h2);
    } else if (idx0 < SEGW1 + SEG2) {
        const float* W = L ? W2b : W2a;
        int i2 = idx0 - SEGW1;
        int n = i2 / HID, k = i2 - n * HID;
        float v = (n < HID) ? W[(size_t)k * HID + n] : 0.0f;
        g_W2t[L][i2] = __float2half_rn(v);
    } else {
        const float* W = L ? W3b : W3a;
        int i3 = idx0 - SEGW1 - SEG2;
        int n = i3 / HID, k = i3 - n * HID;
        float v = (n < POUT) ? W[(size_t)k * POUT + n] : 0.0f;
        g_W3t[L][i3] = __float2half_rn(v);
    }
}

// ================= spline1 table precompute =================
__device__ __forceinline__ float softplus_fast(float v) {
    return fmaxf(v, 0.0f) + __logf(1.0f + __expf(-fabsf(v)));
}

__global__ void k_prepspline(const float* __restrict__ w0, const float* __restrict__ h0,
                             const float* __restrict__ d0, const float* __restrict__ l0,
                             const float* __restrict__ w1, const float* __restrict__ h1,
                             const float* __restrict__ d1, const float* __restrict__ l1) {
    int t = threadIdx.x;
    int L = t >> 8, j = (t >> 4) & 15, b = t & 15;
    const float* wr = (L ? w1 : w0) + j * BINSN;
    const float* hr = (L ? h1 : h0) + j * BINSN;
    const float* dr = (L ? d1 : d0) + j * (BINSN - 1);
    const float* lr = (L ? l1 : l0) + j * BINSN;

    float w[BINSN], h[BINSN];
#pragma unroll
    for (int k = 0; k < BINSN; k++) { w[k] = wr[k]; h[k] = hr[k]; }
    float hm = h[0], wm = w[0];
#pragma unroll
    for (int k = 1; k < BINSN; k++) { hm = fmaxf(hm, h[k]); wm = fmaxf(wm, w[k]); }
    float hs = 0.f, ws = 0.f;
#pragma unroll
    for (int k = 0; k < BINSN; k++) { h[k] = __expf(h[k] - hm); hs += h[k];
                                      w[k] = __expf(w[k] - wm); ws += w[k]; }
    float hscale = 0.984f / hs, wscale = 0.984f / ws;

    float ich = -3.f, ih = 0.f, icw = -3.f, iw = 0.f;
    {
        float prev = -3.f, cs = 0.f;
#pragma unroll
        for (int k = 0; k < BINSN; k++) {
            float hb = 0.001f + hscale * h[k];
            cs += hb;
            float e = (k == BINSN - 1) ? 3.f : fmaf(6.0f, cs, -3.0f);
            if (k == b) { ich = prev; ih = e - prev; }
            prev = e;
        }
    }
    {
        float prev = -3.f, cs = 0.f;
#pragma unroll
        for (int k = 0; k < BINSN; k++) {
            float wb_ = 0.001f + wscale * w[k];
            cs += wb_;
            float e = (k == BINSN - 1) ? 3.f : fmaf(6.0f, cs, -3.0f);
            if (k == b) { icw = prev; iw = e - prev; }
            prev = e;
        }
    }

    float idv   = (b == 0)         ? 0.999f : (0.001f + softplus_fast(dr[b - 1]));
    float idvp1 = (b == BINSN - 1) ? 0.999f : (0.001f + softplus_fast(dr[b]));
    float il    = 0.025f + 0.95f / (1.0f + __expf(-lr[b]));

    float idel = ih / iw;
    float wb   = sqrtf(idv / idvp1);
    float wc   = (il * idv + (1.0f - il) * wb * idvp1) / idel;
    float ya = ich, yb = ih + ich;
    float ym = ((1.0f - il) * ya + il * wb * yb) / ((1.0f - il) + il * wb);
    float dnl = wc * il * (ym - ya) * iw;
    float dnr = wb * wc * (1.0f - il) * (yb - ym) * iw;

    g_sknot[L][j][b] = ich;
    float* e = &g_sbin[L][j][b][0];
    e[0] = ya; e[1] = yb; e[2] = ym; e[3] = iw; e[4] = icw;
    e[5] = il; e[6] = wb; e[7] = wc; e[8] = dnl; e[9] = dnr;
}

// table-driven spline1 eval
__device__ __forceinline__ void spline1_tab(int L, int j, float y, float& xo, float& lo_) {
    bool inside = (y >= -3.f) && (y <= 3.f);
    float yc = fminf(fmaxf(y, -3.f), 3.f);
    const float* kn = &g_sknot[L][j][0];
    int idx = -1;
#pragma unroll
    for (int k = 0; k < 16; k++) idx += (yc >= kn[k]) ? 1 : 0;
    idx = (idx < 0) ? 0 : idx;
    const float* e = &g_sbin[L][j][idx][0];
    float4 e0 = *reinterpret_cast<const float4*>(e);
    float4 e1 = *reinterpret_cast<const float4*>(e + 4);
    float2 e2 = *reinterpret_cast<const float2*>(e + 8);
    float ya = e0.x, yb = e0.y, ym = e0.z, iw = e0.w;
    float icw = e1.x, il = e1.y, wb = e1.z, wc = e1.w;
    bool left = (yc <= ym);
    float num, den, dn;
    if (left) {
        num = il * (ya - yc);
        den = (wc - 1.0f) * yc + ya - wc * ym;
        dn  = e2.x;
    } else {
        num = (wc - il * wb) * yc + il * wb * yb - wc * ym;
        den = (wc - wb) * yc + wb * yb - wc * ym;
        dn  = e2.y;
    }
    float x  = num / den * iw + icw;
    float la = __logf(dn) - 2.0f * __logf(fabsf(den));
    xo  = inside ? x  : y;
    lo_ = inside ? la : 0.0f;
}

// fused H1 = relu(x1 @ W1 + b1): LDS.64 column pairs, c = 2j + 32t
__device__ __forceinline__ void fused_h1(int n, int ln, int j,
                                         const uint32_t* __restrict__ sW1,
                                         const float (*s_x1)[17],
                                         const float* __restrict__ b1) {
    float xv[16];
#pragma unroll
    for (int k = 0; k < 16; k++) xv[k] = s_x1[ln][k];
#pragma unroll 2
    for (int t = 0; t < 10; t++) {
        int c = 2 * j + 32 * t;
        float acc0 = b1[c], acc1 = b1[c + 1];
#pragma unroll
        for (int kp = 0; kp < 8; kp++) {
            uint2 uu = *reinterpret_cast<const uint2*>(&sW1[kp * HID + c]);
            __half2 p0 = *reinterpret_cast<__half2*>(&uu.x);
            __half2 p1 = *reinterpret_cast<__half2*>(&uu.y);
            float2 f0 = __half22float2(p0);
            float2 f1 = __half22float2(p1);
            acc0 = fmaf(xv[2 * kp], f0.x, acc0);
            acc0 = fmaf(xv[2 * kp + 1], f0.y, acc0);
            acc1 = fmaf(xv[2 * kp], f1.x, acc1);
            acc1 = fmaf(xv[2 * kp + 1], f1.y, acc1);
        }
        acc0 = fmaxf(acc0, 0.f);
        acc1 = fmaxf(acc1, 0.f);
        __half2 hv = __floats2half2_rn(acc0, acc1);
        *reinterpret_cast<__half2*>(&g_H1[n * HID + c]) = hv;
    }
}

// per-sample spline inverse from P row; vectorized w/h loads (2x uint4 each)
__device__ __forceinline__ void rls_inv_h(
    float y, const __half* __restrict__ pr, int j,
    float& xo, float& lo_)
{
    const float BD = 3.0f;
    float w[BINSN], h[BINSN];
    {
        const uint4* pw = reinterpret_cast<const uint4*>(pr + j * BINSN);
        const uint4* ph = reinterpret_cast<const uint4*>(pr + 256 + j * BINSN);
        uint4 w0 = pw[0], w1 = pw[1], h0 = ph[0], h1 = ph[1];
        const __half* wh0 = reinterpret_cast<const __half*>(&w0);
        const __half* wh1 = reinterpret_cast<const __half*>(&w1);
        const __half* hh0 = reinterpret_cast<const __half*>(&h0);
        const __half* hh1 = reinterpret_cast<const __half*>(&h1);
#pragma unroll
        for (int b = 0; b < 8; b++) { w[b] = tof(wh0[b]); w[b + 8] = tof(wh1[b]); }
#pragma unroll
        for (int b = 0; b < 8; b++) { h[b] = tof(hh0[b]); h[b + 8] = tof(hh1[b]); }
    }
    const __half* dr = pr + 512 + j * (BINSN - 1);
    const __half* lr = pr + 752 + j * BINSN;

    bool inside = (y >= -BD) && (y <= BD);
    float yc = fminf(fmaxf(y, -BD), BD);

    float hm = h[0], wm = w[0];
#pragma unroll
    for (int b = 1; b < BINSN; b++) { hm = fmaxf(hm, h[b]); wm = fmaxf(wm, w[b]); }
    float hs = 0.f, ws = 0.f;
#pragma unroll
    for (int b = 0; b < BINSN; b++) { h[b] = __expf(h[b] - hm); hs += h[b];
                                      w[b] = __expf(w[b] - wm); ws += w[b]; }
    float hscale = 0.984f / hs;
    float wscale = 0.984f / ws;

    int idx = 0; float ich = -BD, ih = 0.f;
    {
        float prev = -BD, cs = 0.f;
#pragma unroll
        for (int b = 0; b < BINSN; b++) {
            float hb = 0.001f + hscale * h[b];
            cs += hb;
            float e = (b == BINSN - 1) ? BD : fmaf(6.0f, cs, -3.0f);
            if (yc >= prev) { idx = b; ich = prev; ih = e - prev; }
            prev = e;
        }
    }
    float icw = -BD, iw = 0.f;
    {
        float prev = -BD, cs = 0.f;
#pragma unroll
        for (int b = 0; b < BINSN; b++) {
            float wb_ = 0.001f + wscale * w[b];
            cs += wb_;
            float e = (b == BINSN - 1) ? BD : fmaf(6.0f, cs, -3.0f);
            if (b == idx) { icw = prev; iw = e - prev; }
            prev = e;
        }
    }

    float idv   = (idx == 0)         ? 0.999f : (0.001f + softplus_fast(tof(dr[idx - 1])));
    float idvp1 = (idx == BINSN - 1) ? 0.999f : (0.001f + softplus_fast(tof(dr[idx])));
    float il    = 0.025f + 0.95f / (1.0f + __expf(-tof(lr[idx])));

    float idel = ih / iw;
    float wb   = sqrtf(idv / idvp1);
    float wc   = (il * idv + (1.0f - il) * wb * idvp1) / idel;
    float ya = ich, yb = ih + ich;
    float ym = ((1.0f - il) * ya + il * wb * yb) / ((1.0f - il) + il * wb);

    bool left = (yc <= ym);
    float num, den, dnum;
    if (left) {
        num  = il * (ya - yc);
        den  = (wc - 1.0f) * yc + ya - wc * ym;
        dnum = wc * il * (ym - ya) * iw;
    } else {
        num  = (wc - il * wb) * yc + il * wb * yb - wc * ym;
        den  = (wc - wb) * yc + wb * yb - wc * ym;
        dnum = wb * wc * (1.0f - il) * (yb - ym) * iw;
    }
    float x  = num / den * iw + icw;
    float la = __logf(dnum) - 2.0f * __logf(fabsf(den));

    xo  = inside ? x  : y;
    lo_ = inside ? la : 0.0f;
}

__device__ __forceinline__ void spline2_step(int n, int j, float& x2, float& ladj_acc) {
    float y = g_z[n * DD + SPLITD + j];
    const __half* pr = g_P + (size_t)n * POUT;
    float la;
    rls_inv_h(y, pr, j, x2, la);
    ladj_acc += la;
}

// first kernel
__global__ void __launch_bounds__(256) k_first(const float* __restrict__ data,
                        const float* __restrict__ means,
                        const float* __restrict__ stds,
                        const float* __restrict__ b1) {
    __shared__ uint32_t sW1[8 * HID];
    __shared__ float s_x1[16][17];
    int tid = threadIdx.x;
#pragma unroll
    for (int u = tid; u < 8 * HID; u += 256) sW1[u] = g_W1s[0][u];

    int i = blockIdx.x * 256 + tid;
    int n = i >> 4, j = i & 15, ln = tid >> 4;
    float y  = (data[n * DD + j]      - means[j])      / (10.0f * stds[j]);
    float y2 = (data[n * DD + j + 16] - means[j + 16]) / (10.0f * stds[j + 16]);
    g_z[n * DD + j + 16] = y2;
    float x, la;
    spline1_tab(0, j, y, x, la);
    g_z[n * DD + j] = x;
    g_ladj[i] = la;
    s_x1[ln][j] = x;
    __syncthreads();
    fused_h1(n, ln, j, sW1, s_x1, b1);
}

// mid kernel
__global__ void __launch_bounds__(256) k_mid(const float* __restrict__ b1) {
    __shared__ uint32_t sW1[8 * HID];
    __shared__ float s_x1[16][17];
    int tid = threadIdx.x;
#pragma unroll
    for (int u = tid; u < 8 * HID; u += 256) sW1[u] = g_W1s[1][u];

    int i = blockIdx.x * 256 + tid;
    int n = i >> 4, j = i & 15, ln = tid >> 4;
    float ladj = g_ladj[i];
    float x2;
    spline2_step(n, j, x2, ladj);
    g_z[n * DD + SPLITD + j] = x2;

    float y1 = g_z[n * DD + j];
    float x1, la1;
    spline1_tab(1, j, y1, x1, la1);
    g_z[n * DD + j] = x1;
    g_ladj[i] = ladj + la1;
    s_x1[ln][j] = x1;
    __syncthreads();
    fused_h1(n, ln, j, sW1, s_x1, b1);
}

// last kernel
__global__ void k_last(const float* __restrict__ stds, float* __restrict__ out) {
    __shared__ float s_lp;
    if (threadIdx.x < 32) {
        float v = logf(10.0f * stds[threadIdx.x]);
#pragma unroll
        for (int o = 16; o > 0; o >>= 1) v += __shfl_down_sync(0xffffffffu, v, o);
        if (threadIdx.x == 0) s_lp = -v;
    }
    __syncthreads();
    int i = blockIdx.x * blockDim.x + threadIdx.x;
    int n = i >> 4, j = i & 15;
    float ladj = g_ladj[i];
    float x2;
    spline2_step(n, j, x2, ladj);
    float z1 = g_z[n * DD + j];
    float ss = fmaf(z1, z1, x2 * x2);
#pragma unroll
    for (int o = 1; o < 16; o <<= 1) {
        ss   += __shfl_xor_sync(0xffffffffu, ss, o);
        ladj += __shfl_xor_sync(0xffffffffu, ladj, o);
    }
    if ((threadIdx.x & 15) == 0)
        out[n] = -0.5f * ss - 0.5f * (float)DD * LOG2PI_F + ladj + s_lp;
}

// ====== HMMA fp16 GEMM (R12 best): BK=64, 4 warps, warp tile 32x128, 2-stage ====
#define RSTR    144
#define TILE_B  (128 * RSTR)
#define STAGE_B (2 * TILE_B)
#define SM_TOTAL (2 * STAGE_B)        // 73728

template <bool RELU>
__global__ void __launch_bounds__(128) hgemm(
    const __half* __restrict__ A,
    const __half* __restrict__ B,
    const float* __restrict__ bias,
    int K, int Nreal, int ldc,
    __half* __restrict__ C)
{
    extern __shared__ char smem[];
    const uint32_t sb = smem_u32(smem);
    const int tid = threadIdx.x;
    const int wid = tid >> 5, lane = tid & 31;

    const int brow = blockIdx.y * 128;
    const int bcol = blockIdx.x * 128;
    const int nch = K >> 6;

    float acc[2][16][4];
#pragma unroll
    for (int i = 0; i < 2; i++)
#pragma unroll
        for (int j = 0; j < 16; j++)
#pragma unroll
            for (int q = 0; q < 4; q++) acc[i][j][q] = 0.f;

    auto load_chunk = [&](int ch, int stage) {
        const int k0 = ch * 64;
        const uint32_t sbase = sb + stage * STAGE_B;
#pragma unroll
        for (int u = 0; u < 16; u++) {
            int idx = tid + u * 128;
            int mat = idx >> 10;
            int wi  = idx & 1023;
            int r = wi >> 3, c = wi & 7;
            uint32_t so = (uint32_t)(mat * TILE_B + r * RSTR + c * 16);
            const __half* src = (mat == 0) ? (A + (size_t)(brow + r) * K + k0 + c * 8)
                                           : (B + (size_t)(bcol + r) * K + k0 + c * 8);
            cp16(sbase + so, src);
        }
        asm volatile("cp.async.commit_group;" ::: "memory");
    };

    load_chunk(0, 0);

    for (int ch = 0; ch < nch; ch++) {
        if (ch + 1 < nch) {
            load_chunk(ch + 1, (ch + 1) & 1);
            asm volatile("cp.async.wait_group 1;" ::: "memory");
        } else {
            asm volatile("cp.async.wait_group 0;" ::: "memory");
        }
        __syncthreads();

        const uint32_t sbase = sb + (ch & 1) * STAGE_B;
        const uint32_t abase = sbase;
        const uint32_t bbase = sbase + TILE_B;

#pragma unroll
        for (int ks = 0; ks < 4; ks++) {
            uint32_t a[2][4];
            const uint32_t arow = (uint32_t)(wid * 32 + (lane & 15));
            const uint32_t akb  = (uint32_t)(ks * 32 + ((lane >> 4) & 1) * 16);
#pragma unroll
            for (int tm = 0; tm < 2; tm++) {
                uint32_t off = (arow + tm * 16) * RSTR + akb;
                ldsm4(a[tm][0], a[tm][1], a[tm][2], a[tm][3], abase + off);
            }
            uint32_t bf[16][2];
            const uint32_t nrow0 = (uint32_t)((lane & 7) + ((lane >> 4) & 1) * 8);
            const uint32_t bkb   = (uint32_t)(ks * 32 + ((lane >> 3) & 1) * 16);
#pragma unroll
            for (int tp = 0; tp < 8; tp++) {
                uint32_t off = (nrow0 + tp * 16) * RSTR + bkb;
                ldsm4(bf[tp * 2][0], bf[tp * 2][1], bf[tp * 2 + 1][0], bf[tp * 2 + 1][1], bbase + off);
            }
#pragma unroll
            for (int tm = 0; tm < 2; tm++)
#pragma unroll
                for (int tn = 0; tn < 16; tn++)
                    mma_f16(acc[tm][tn], a[tm], bf[tn]);
        }
        __syncthreads();
    }

#pragma unroll
    for (int tm = 0; tm < 2; tm++) {
#pragma unroll
        for (int tn = 0; tn < 16; tn++) {
            int n = bcol + tn * 8 + 2 * (lane & 3);
            if (n >= Nreal) continue;
            float bb0 = bias[n], bb1 = bias[n + 1];
#pragma unroll
            for (int half = 0; half < 2; half++) {
                int m = brow + wid * 32 + tm * 16 + (lane >> 2) + half * 8;
                float v0 = acc[tm][tn][half * 2 + 0] + bb0;
                float v1 = acc[tm][tn][half * 2 + 1] + bb1;
                if (RELU) { v0 = fmaxf(v0, 0.f); v1 = fmaxf(v1, 0.f); }
                __half2 hv = __floats2half2_rn(v0, v1);
                *reinterpret_cast<__half2*>(C + (size_t)m * ldc + n) = hv;
            }
        }
    }
}

// ================= launch =================
extern "C" void kernel_launch(void* const* d_in, const int* in_sizes, int n_in,
                              void* d_out, int out_size) {
    const float* data  = (const float*)d_in[0];
    const float* means = (const float*)d_in[1];
    const float* stds  = (const float*)d_in[2];

    const float* tw[2]  = { (const float*)d_in[13], (const float*)d_in[3] };
    const float* th[2]  = { (const float*)d_in[14], (const float*)d_in[4] };
    const float* td[2]  = { (const float*)d_in[15], (const float*)d_in[5] };
    const float* tl[2]  = { (const float*)d_in[16], (const float*)d_in[6] };
    const float* tW1[2] = { (const float*)d_in[17], (const float*)d_in[7] };
    const float* tb1[2] = { (const float*)d_in[18], (const float*)d_in[8] };
    const float* tW2[2] = { (const float*)d_in[19], (const float*)d_in[9] };
    const float* tb2[2] = { (const float*)d_in[20], (const float*)d_in[10] };
    const float* tW3[2] = { (const float*)d_in[21], (const float*)d_in[11] };
    const float* tb3[2] = { (const float*)d_in[22], (const float*)d_in[12] };

    float* out = (float*)d_out;

    __half *H1, *H2, *pP;
    __half *W2t0, *W3t0;
    cudaGetSymbolAddress((void**)&H1,  g_H1);
    cudaGetSymbolAddress((void**)&H2,  g_H2);
    cudaGetSymbolAddress((void**)&pP,  g_P);
    cudaGetSymbolAddress((void**)&W2t0, g_W2t);
    cudaGetSymbolAddress((void**)&W3t0, g_W3t);

    cudaFuncSetAttribute(hgemm<true >, cudaFuncAttributeMaxDynamicSharedMemorySize, SM_TOTAL);
    cudaFuncSetAttribute(hgemm<false>, cudaFuncAttributeMaxDynamicSharedMemorySize, SM_TOTAL);

    const int splineBlocks = (NS * SPLITD) / 256;
    dim3 g12(NP12 / 128, NS / 128);  // (3, 256)
    dim3 g3 (NP3  / 128, NS / 128);  // (8, 256)

    k_prepall<<<(2 * PREP_TOT + 255) / 256, 256>>>(tW1[0], tW2[0], tW3[0],
                                                   tW1[1], tW2[1], tW3[1]);
    k_prepspline<<<1, 512>>>(tw[0], th[0], td[0], tl[0], tw[1], th[1], td[1], tl[1]);

    k_first<<<splineBlocks, 256>>>(data, means, stds, tb1[0]);

    for (int L = 0; L < 2; L++) {
        __half* W2t = W2t0 + (size_t)L * SEG2;
        __half* W3t = W3t0 + (size_t)L * SEG3;

        hgemm<true ><<<g12, 128, SM_TOTAL>>>(H1, W2t, tb2[L], HID, HID, HID, H2);
        hgemm<false><<<g3,  128, SM_TOTAL>>>(H2, W3t, tb3[L], HID, POUT, POUT, pP);

        if (L == 0)
            k_mid<<<splineBlocks, 256>>>(tb1[1]);
        else
            k_last<<<splineBlocks, 256>>>(stds, out);
    }
}